// round 15
// baseline (speedup 1.0000x reference)
#include <cuda_runtime.h>
#include <cstdint>

#define BT 1024
#define NB 4096
#define ESTR 224          // smem bytes per element
#define XOFF 6144         // floats per element row (BT*6)
#define XOFF64 3072       // u64 per element row

typedef unsigned long long u64;

__device__ __forceinline__ u64 pk2(float lo, float hi) {
    u64 r; asm("mov.b64 %0, {%1,%2};" : "=l"(r) : "f"(lo), "f"(hi)); return r;
}
__device__ __forceinline__ void unpk2(u64 p, float& lo, float& hi) {
    asm("mov.b64 {%0,%1}, %2;" : "=f"(lo), "=f"(hi) : "l"(p));
}
__device__ __forceinline__ u64 ffma2(u64 a, u64 b, u64 c) {
    u64 d; asm("fma.rn.f32x2 %0, %1, %2, %3;" : "=l"(d) : "l"(a), "l"(b), "l"(c)); return d;
}
__device__ __forceinline__ u64 fmul2(u64 a, u64 b) {
    u64 d; asm("mul.rn.f32x2 %0, %1, %2;" : "=l"(d) : "l"(a), "l"(b)); return d;
}
__device__ __forceinline__ u64 fadd2(u64 a, u64 b) {
    u64 d; asm("add.rn.f32x2 %0, %1, %2;" : "=l"(d) : "l"(a), "l"(b)); return d;
}
__device__ __forceinline__ float ex2f(float x) {
    float y; asm("ex2.approx.f32 %0, %1;" : "=f"(y) : "f"(x)); return y;
}
__device__ __forceinline__ float rcpf(float x) {
    float y; asm("rcp.approx.f32 %0, %1;" : "=f"(y) : "f"(x)); return y;
}

// Reduction-dim f32x2 packed weights, gate scales pre-folded (i/f/o: -log2e, g: +2log2e).
struct CellW { u64 WA[4][3], WB[4][3], BA[4]; };

// Fused-activation LSTM cell (5 EX2 + 3 RCP):
//   i*g = (Eg-1)*rcp((Eg+1)(Ei+1));  f*c = c*rcp(Ef+1)
//   h   = (Ec-1)*rcp((Ec+1)(Eo+1)),  Ec = ex2(min(2log2e*c, 100))
__device__ __forceinline__ void cell(const CellW& w, const u64* A, const u64* Bp,
                                     float cin, float& cn, float& hn)
{
    float z[4];
#pragma unroll
    for (int q = 0; q < 4; ++q) {
        u64 a = ffma2(w.WA[q][0], A[0], w.BA[q]);
        a = ffma2(w.WA[q][1], A[1], a);
        a = ffma2(w.WA[q][2], A[2], a);
        u64 bb = fmul2(w.WB[q][0], Bp[0]);
        bb = ffma2(w.WB[q][1], Bp[1], bb);
        bb = ffma2(w.WB[q][2], Bp[2], bb);
        a = fadd2(a, bb);
        float lo, hi; unpk2(a, lo, hi);
        z[q] = lo + hi;
    }
    float Ei = ex2f(z[0]), Ef = ex2f(z[1]), Eg = ex2f(z[2]), Eo = ex2f(z[3]);
    float ig = (Eg - 1.0f) * rcpf((Eg + 1.0f) * (Ei + 1.0f));
    cn = fmaf(cin, rcpf(Ef + 1.0f), ig);
    float zc = fminf(cn * 2.8853900817779268f, 100.0f);
    float Ec = ex2f(zc);
    hn = (Ec - 1.0f) * rcpf((Ec + 1.0f) * (Eo + 1.0f));
}

// smem per element (ESTR=224B):
//   X region [0,96):  4 slots * 24B  (x[t] pairs)
//   H region [96,192): 2 slots * 48B: [0,24)=h0, [24,48)=h1
// Body t: layer0 lanes -> h0[t], layer1 lanes -> h1[t-1] (stored to gmem).
// layer1's A-input = h0[t-1], read directly from the H read-slot (no duplicate store).
// x staging: body t LDGs x[t+5], STSs x[t+3] (1 u64/stager lane per element).
// ILP-2: each lane runs TWO elements (offsets +224 smem, +XOFF gmem) off ONE weight set.

#define BODY(P,BR,BW,XS,Q,LDI,STI,DOLDG,DOSTSX,DOSTG) do {                   \
    u64 A0_[3], B0_[3], A1_[3], B1_[3];                                      \
    A0_[0] = *(const u64*)(aA[P] + 0);                                       \
    A0_[1] = *(const u64*)(aA[P] + 8);                                       \
    A0_[2] = *(const u64*)(aA[P] + 16);                                      \
    A1_[0] = *(const u64*)(aA[P] + ESTR + 0);                                \
    A1_[1] = *(const u64*)(aA[P] + ESTR + 8);                                \
    A1_[2] = *(const u64*)(aA[P] + ESTR + 16);                               \
    B0_[0] = *(const u64*)(bb_base + (BR)*48 + 0);                           \
    B0_[1] = *(const u64*)(bb_base + (BR)*48 + 8);                           \
    B0_[2] = *(const u64*)(bb_base + (BR)*48 + 16);                          \
    B1_[0] = *(const u64*)(bb_base + ESTR + (BR)*48 + 0);                    \
    B1_[1] = *(const u64*)(bb_base + ESTR + (BR)*48 + 8);                    \
    B1_[2] = *(const u64*)(bb_base + ESTR + (BR)*48 + 16);                   \
    float cn0_, hn0_, cn1_, hn1_;                                            \
    cell(W, A0_, B0_, c0v, cn0_, hn0_);                                      \
    cell(W, A1_, B1_, c1v, cn1_, hn1_);                                      \
    c0v = cn0_; h0v = hn0_; c1v = cn1_; h1v = hn1_;                          \
    if ((DOSTG) && is_l1) { og_run[(STI)] = hn0_; og_run[XOFF + (STI)] = hn1_; } \
    *(float*)(hst_base + (BW)*48) = h0v;                                     \
    *(float*)(hst_base + ESTR + (BW)*48) = h1v;                              \
    if ((DOSTSX) && stager) {                                                \
        *(u64*)(xst_base + (XS)*24) = xqa[(Q)];                              \
        *(u64*)(xst_base + ESTR + (XS)*24) = xqb[(Q)];                       \
    }                                                                        \
    if ((DOLDG) && stager) {                                                 \
        xqa[(Q)] = __ldg(xg_run + (LDI));                                    \
        xqb[(Q)] = __ldg(xg_run + XOFF64 + (LDI));                           \
    }                                                                        \
    __syncwarp(0x00ffffffu);                                                 \
} while (0)

__global__ void __launch_bounds__(64)
lstm2_kernel(const float* __restrict__ x,
             const float* __restrict__ wih0, const float* __restrict__ whh0,
             const float* __restrict__ bih0, const float* __restrict__ bhh0,
             const float* __restrict__ wih1, const float* __restrict__ whh1,
             const float* __restrict__ bih1, const float* __restrict__ bhh1,
             float* __restrict__ out)
{
    __shared__ __align__(16) char sm[2 * 4 * ESTR];   // 2 warps * 4 elements

    const int lane = threadIdx.x & 31;
    if (lane >= 24) return;                  // 2 groups of 12 lanes per warp
    const int w_in = threadIdx.x >> 5;
    const int g = lane / 12;                 // lane group: serves elem pair
    const int r = lane % 12;
    const bool is_l1 = (r >= 6);
    const int j = r % 6;
    const int warp = blockIdx.x * 2 + w_in;
    const int bpair = warp * 4 + g * 2;      // elements bpair, bpair+1 (1024 warps exact)
    const bool stager = (!is_l1) && (j < 3);

    char* E0 = sm + w_in * (4 * ESTR) + g * (2 * ESTR);   // elem0 region (+ESTR = elem1)

    // Per-phase A pointers: phases p0..p3 = (TP,BR) of (1,0),(2,1),(3,0),(0,1).
    // layer0 reads x slot TP; layer1 reads h0 part of H read-slot BR.
    const int TPs[4] = {1, 2, 3, 0};
    const int BRs[4] = {0, 1, 0, 1};
    char* aA[4];
#pragma unroll
    for (int p = 0; p < 4; ++p)
        aA[p] = is_l1 ? (E0 + 96 + BRs[p] * 48) : (E0 + TPs[p] * 24);

    char* bb_base  = E0 + 96 + (is_l1 ? 24 : 0);   // + BR*48 (+ESTR for elem1)
    char* hst_base = E0 + 96 + r * 4;              // + BW*48
    char* xst_base = E0 + j * 8;                   // + XS*24 (stagers only)

    const float SSIG = -1.4426950408889634f;   // -log2(e)
    const float SGc  =  2.8853900817779268f;   //  2*log2(e)

    const float* Wih = is_l1 ? wih1 : wih0;
    const float* Whh = is_l1 ? whh1 : whh0;
    const float* Bih = is_l1 ? bih1 : bih0;
    const float* Bhh = is_l1 ? bhh1 : bhh0;

    CellW W;                                   // shared by BOTH elements of this lane
#pragma unroll
    for (int q = 0; q < 4; ++q) {              // q: 0=i 1=f 2=g 3=o
        const int row = j + 6 * q;
        const float s = (q == 2) ? SGc : SSIG;
#pragma unroll
        for (int m = 0; m < 3; ++m) {
            W.WA[q][m] = pk2(Wih[row * 6 + 2 * m] * s, Wih[row * 6 + 2 * m + 1] * s);
            W.WB[q][m] = pk2(Whh[row * 6 + 2 * m] * s, Whh[row * 6 + 2 * m + 1] * s);
        }
        W.BA[q] = pk2((Bih[row] + Bhh[row]) * s, 0.0f);
    }

    const u64* xg_run = (const u64*)(x + (size_t)bpair * XOFF) + j;  // elem1: +XOFF64
    float* og_run = out + (size_t)bpair * XOFF + j;                  // elem1: +XOFF
    float h0v = 0.f, c0v = 0.f, h1v = 0.f, c1v = 0.f;
    u64 xqa[2] = {0ull, 0ull}, xqb[2] = {0ull, 0ull};

    // ---- prologue: zero H slot1, stage x[0..2], prime xq=x[3],x[4] ----
    *(float*)(hst_base + 48) = 0.f;
    *(float*)(hst_base + ESTR + 48) = 0.f;
    if (stager) {
#pragma unroll
        for (int s = 0; s < 3; ++s) {
            *(u64*)(xst_base + s * 24)        = __ldg(xg_run + s * 3);
            *(u64*)(xst_base + ESTR + s * 24) = __ldg(xg_run + XOFF64 + s * 3);
        }
        xqa[0] = __ldg(xg_run + 9);  xqa[1] = __ldg(xg_run + 12);
        xqb[0] = __ldg(xg_run + XOFF64 + 9); xqb[1] = __ldg(xg_run + XOFF64 + 12);
    }
    __syncwarp(0x00ffffffu);

    // ---- peel t=0: aA[3] = (x slot0 | h0 slot1=0); B slot1 (zeros); commit l0 only ----
    {
        u64 A0_[3], B0_[3], A1_[3], B1_[3];
#pragma unroll
        for (int m = 0; m < 3; ++m) {
            A0_[m] = *(const u64*)(aA[3] + m * 8);
            A1_[m] = *(const u64*)(aA[3] + ESTR + m * 8);
            B0_[m] = *(const u64*)(bb_base + 48 + m * 8);
            B1_[m] = *(const u64*)(bb_base + ESTR + 48 + m * 8);
        }
        float cn0_, hn0_, cn1_, hn1_;
        cell(W, A0_, B0_, c0v, cn0_, hn0_);
        cell(W, A1_, B1_, c1v, cn1_, hn1_);
        if (!is_l1) { c0v = cn0_; h0v = hn0_; c1v = cn1_; h1v = hn1_; }
        *(float*)(hst_base + 0) = h0v;                       // BW=0
        *(float*)(hst_base + ESTR + 0) = h1v;
        if (stager) {
            *(u64*)(xst_base + 3 * 24) = xqa[0];             // x[3] -> slot 3
            *(u64*)(xst_base + ESTR + 3 * 24) = xqb[0];
            xqa[0] = __ldg(xg_run + 15);                     // x[5]
            xqb[0] = __ldg(xg_run + XOFF64 + 15);
        }
        __syncwarp(0x00ffffffu);
    }
    xg_run += 3;   // t_base = 1

    // ---- main: t = 1..1016 (254 groups of 4) ----
#pragma unroll 1
    for (int gg = 0; gg < 254; ++gg) {
        //   P  BR BW XS Q  LDI STI
        BODY(0, 0, 1, 0, 1, 15,  0, true, true, true);   // t%4==1
        BODY(1, 1, 0, 1, 0, 18,  6, true, true, true);   // t%4==2
        BODY(2, 0, 1, 2, 1, 21, 12, true, true, true);   // t%4==3
        BODY(3, 1, 0, 3, 0, 24, 18, true, true, true);   // t%4==0
        xg_run += 12;
        og_run += 24;
    }

    // ---- tail: t = 1017..1023 ----
    BODY(0, 0, 1, 0, 1, 15,  0, true,  true,  true);   // t=1017: LDG x[1022], STS x[1020]
    BODY(1, 1, 0, 1, 0, 18,  6, true,  true,  true);   // t=1018: LDG x[1023], STS x[1021]
    BODY(2, 0, 1, 2, 1,  0, 12, false, true,  true);   // t=1019: STS x[1022]
    BODY(3, 1, 0, 3, 0,  0, 18, false, true,  true);   // t=1020: STS x[1023]
    BODY(0, 0, 1, 0, 1,  0, 24, false, false, true);   // t=1021
    BODY(1, 1, 0, 1, 0,  0, 30, false, false, true);   // t=1022
    BODY(2, 0, 1, 2, 1,  0, 36, false, false, true);   // t=1023

    // ---- epilogue t=1024: layer1 computes & stores h1[1023] (reads slot1) ----
    {
        u64 A0_[3], B0_[3], A1_[3], B1_[3];
#pragma unroll
        for (int m = 0; m < 3; ++m) {
            A0_[m] = *(const u64*)(aA[3] + m * 8);           // l1: h0[1023]
            A1_[m] = *(const u64*)(aA[3] + ESTR + m * 8);
            B0_[m] = *(const u64*)(bb_base + 48 + m * 8);    // l1: h1[1022]
            B1_[m] = *(const u64*)(bb_base + ESTR + 48 + m * 8);
        }
        float cn0_, hn0_, cn1_, hn1_;
        cell(W, A0_, B0_, c0v, cn0_, hn0_);
        cell(W, A1_, B1_, c1v, cn1_, hn1_);
        if (is_l1) { og_run[42] = hn0_; og_run[XOFF + 42] = hn1_; }
    }
}

extern "C" void kernel_launch(void* const* d_in, const int* in_sizes, int n_in,
                              void* d_out, int out_size)
{
    const float* x    = (const float*)d_in[0];
    const float* wih0 = (const float*)d_in[1];
    const float* whh0 = (const float*)d_in[2];
    const float* bih0 = (const float*)d_in[3];
    const float* bhh0 = (const float*)d_in[4];
    const float* wih1 = (const float*)d_in[5];
    const float* whh1 = (const float*)d_in[6];
    const float* bih1 = (const float*)d_in[7];
    const float* bhh1 = (const float*)d_in[8];
    float* out = (float*)d_out;

    // 4096 elements, 4 per warp (ILP-2 per lane), 1024 warps -> 512 CTAs * 64 threads
    lstm2_kernel<<<512, 64>>>(x, wih0, whh0, bih0, bhh0,
                              wih1, whh1, bih1, bhh1, out);
}